// round 1
// baseline (speedup 1.0000x reference)
#include <cuda_runtime.h>
#include <cuda_bf16.h>

#define B_ 8
#define T_ 256
#define U_ 65
#define D_ 512
#define BTU_ (B_ * T_ * U_)
#define BLANK_ (D_ - 1)

// Scratch: per-(b,t,u) blank and label log-probs (device globals, no allocation).
__device__ float g_blank[BTU_];
__device__ float g_label[BTU_];

// ---------------------------------------------------------------------------
// Kernel 1: per-row logsumexp over D=512; emit blank_lp and label_lp.
// One warp per row. Each lane loads 4x float4 (16 floats), coalesced 512B/warp
// per iteration. Reads 272MB once -> HBM-bound.
// ---------------------------------------------------------------------------
__global__ void __launch_bounds__(256) lse_kernel(const float* __restrict__ logits,
                                                  const int* __restrict__ targets) {
    const int gw = (blockIdx.x * 256 + threadIdx.x) >> 5;   // global warp = row id
    const int lane = threadIdx.x & 31;
    if (gw >= BTU_) return;

    const float4* row4 = reinterpret_cast<const float4*>(logits + (size_t)gw * D_);
    const float4 v0 = row4[lane];
    const float4 v1 = row4[lane + 32];
    const float4 v2 = row4[lane + 64];
    const float4 v3 = row4[lane + 96];

    // local max of 16
    float m = v0.x;
    m = fmaxf(m, v0.y); m = fmaxf(m, v0.z); m = fmaxf(m, v0.w);
    m = fmaxf(m, v1.x); m = fmaxf(m, v1.y); m = fmaxf(m, v1.z); m = fmaxf(m, v1.w);
    m = fmaxf(m, v2.x); m = fmaxf(m, v2.y); m = fmaxf(m, v2.z); m = fmaxf(m, v2.w);
    m = fmaxf(m, v3.x); m = fmaxf(m, v3.y); m = fmaxf(m, v3.z); m = fmaxf(m, v3.w);
#pragma unroll
    for (int o = 16; o; o >>= 1) m = fmaxf(m, __shfl_xor_sync(0xffffffffu, m, o));

    // sum of exp(v - m)
    float s = 0.f;
    s += __expf(v0.x - m) + __expf(v0.y - m) + __expf(v0.z - m) + __expf(v0.w - m);
    s += __expf(v1.x - m) + __expf(v1.y - m) + __expf(v1.z - m) + __expf(v1.w - m);
    s += __expf(v2.x - m) + __expf(v2.y - m) + __expf(v2.z - m) + __expf(v2.w - m);
    s += __expf(v3.x - m) + __expf(v3.y - m) + __expf(v3.z - m) + __expf(v3.w - m);
#pragma unroll
    for (int o = 16; o; o >>= 1) s += __shfl_xor_sync(0xffffffffu, s, o);

    const float lse = m + __logf(s);

    // blank logit = element 511 = lane31's v3.w
    const float blankLogit = __shfl_sync(0xffffffffu, v3.w, 31);

    if (lane == 0) {
        const int u = gw % U_;
        const int b = gw / (T_ * U_);
        const int lbl = (u < U_ - 1) ? targets[b * (U_ - 1) + u] : 0;  // padded col -> 0
        const float labelLogit = __ldg(logits + (size_t)gw * D_ + lbl);
        g_blank[gw] = blankLogit - lse;
        g_label[gw] = labelLogit - lse;
    }
}

// ---------------------------------------------------------------------------
// Kernel 2: alpha DP per batch via anti-diagonal wavefront.
// One CTA per batch; full blank/label tiles (2 * 66560 B) staged in dyn SMEM.
// ---------------------------------------------------------------------------
extern __shared__ float s_dyn[];

__global__ void __launch_bounds__(128) dp_kernel(const int* __restrict__ srcLen,
                                                 const int* __restrict__ tgtLen,
                                                 float* __restrict__ out) {
    const int b = blockIdx.x;
    const int tid = threadIdx.x;

    float* sBlank = s_dyn;            // [T_*U_]
    float* sLabel = s_dyn + T_ * U_;  // [T_*U_]
    __shared__ float diag0[U_];
    __shared__ float diag1[U_];
    __shared__ float sFinal;

    // Stage both tiles from L2 (written by kernel 1) into SMEM, float4 coalesced.
    {
        const float4* gb = reinterpret_cast<const float4*>(g_blank + b * T_ * U_);
        const float4* gl = reinterpret_cast<const float4*>(g_label + b * T_ * U_);
        float4* sb = reinterpret_cast<float4*>(sBlank);
        float4* sl = reinterpret_cast<float4*>(sLabel);
#pragma unroll 4
        for (int i = tid; i < (T_ * U_) / 4; i += 128) {
            sb[i] = gb[i];
            sl[i] = gl[i];
        }
    }
    __syncthreads();

    const int tE = srcLen[b] - 1;
    const int uE = tgtLen[b];
    const int dE = tE + uE;

    float* prev = diag0;
    float* cur = diag1;

    for (int d = 0; d <= (T_ - 1) + (U_ - 1); ++d) {
        const int ulo = (d - (T_ - 1) > 0) ? (d - (T_ - 1)) : 0;
        const int uhi = (d < U_ - 1) ? d : (U_ - 1);
        for (int u = ulo + tid; u <= uhi; u += 128) {
            const int t = d - u;
            float val;
            if (t == 0) {
                // alpha[0][u] = alpha[0][u-1] + label_lp[0][u-1]; alpha[0][0] = 0
                val = (u == 0) ? 0.0f : prev[u - 1] + sLabel[u - 1];
            } else if (u == 0) {
                val = prev[0] + sBlank[(t - 1) * U_];
            } else {
                const float a = prev[u] + sBlank[(t - 1) * U_ + u];
                const float c = prev[u - 1] + sLabel[t * U_ + (u - 1)];
                const float mx = fmaxf(a, c);
                const float mn = fminf(a, c);
                val = mx + log1pf(__expf(mn - mx));
            }
            cur[u] = val;
            if (d == dE && u == uE) sFinal = val;
        }
        __syncthreads();
        float* tmp = prev; prev = cur; cur = tmp;
    }

    if (tid == 0) {
        out[b] = -(sFinal + sBlank[tE * U_ + uE]);
    }
}

// ---------------------------------------------------------------------------
extern "C" void kernel_launch(void* const* d_in, const int* in_sizes, int n_in,
                              void* d_out, int out_size) {
    const float* logits = (const float*)d_in[0];
    const int* targets = (const int*)d_in[1];
    const int* srcLen = (const int*)d_in[2];
    const int* tgtLen = (const int*)d_in[3];
    float* out = (float*)d_out;

    // Kernel 1: one warp per row, 8 warps per block.
    lse_kernel<<<BTU_ / 8, 256>>>(logits, targets);

    // Kernel 2: one block per batch, 130KB dynamic smem (opt-in each call; idempotent).
    const int smemBytes = 2 * T_ * U_ * (int)sizeof(float);
    cudaFuncSetAttribute(dp_kernel, cudaFuncAttributeMaxDynamicSharedMemorySize, smemBytes);
    dp_kernel<<<B_, 128, smemBytes>>>(srcLen, tgtLen, out);
}

// round 2
// speedup vs baseline: 1.1381x; 1.1381x over previous
#include <cuda_runtime.h>
#include <cuda_bf16.h>

#define B_ 8
#define T_ 256
#define U_ 65
#define D_ 512
#define BTU_ (B_ * T_ * U_)
#define SROW 66                 // padded row stride (floats) for blank/label tiles

#define NEG (-1.0e30f)
#define INV_LN2 1.4426950408889634f
#define LN2 0.6931471805599453f

// Scratch: per-(b,t,u) blank/label log2-probs, padded stride 66 (device globals).
__device__ float g_blank[B_ * T_ * SROW];
__device__ float g_label[B_ * T_ * SROW];

__device__ __forceinline__ float ex2f(float x) {
    float y; asm("ex2.approx.ftz.f32 %0, %1;" : "=f"(y) : "f"(x)); return y;
}
__device__ __forceinline__ float lg2f(float x) {
    float y; asm("lg2.approx.ftz.f32 %0, %1;" : "=f"(y) : "f"(x)); return y;
}
// logaddexp in log2 domain: mx + log2(1 + 2^(mn-mx))
__device__ __forceinline__ float lae2(float a, float b) {
    float mx = fmaxf(a, b);
    float mn = fminf(a, b);
    return mx + lg2f(1.0f + ex2f(mn - mx));
}

// ---------------------------------------------------------------------------
// Kernel 1: per-row logsumexp over D=512; emit blank/label log2-probs.
// One warp per row, 4x float4 per lane. HBM-bound (reads 272MB once).
// ---------------------------------------------------------------------------
__global__ void __launch_bounds__(256) lse_kernel(const float* __restrict__ logits,
                                                  const int* __restrict__ targets) {
    const int gw = (blockIdx.x * 256 + threadIdx.x) >> 5;   // row id in [0, BTU)
    const int lane = threadIdx.x & 31;
    if (gw >= BTU_) return;

    const float4* row4 = reinterpret_cast<const float4*>(logits + (size_t)gw * D_);
    const float4 v0 = row4[lane];
    const float4 v1 = row4[lane + 32];
    const float4 v2 = row4[lane + 64];
    const float4 v3 = row4[lane + 96];

    float m = v0.x;
    m = fmaxf(m, v0.y); m = fmaxf(m, v0.z); m = fmaxf(m, v0.w);
    m = fmaxf(m, v1.x); m = fmaxf(m, v1.y); m = fmaxf(m, v1.z); m = fmaxf(m, v1.w);
    m = fmaxf(m, v2.x); m = fmaxf(m, v2.y); m = fmaxf(m, v2.z); m = fmaxf(m, v2.w);
    m = fmaxf(m, v3.x); m = fmaxf(m, v3.y); m = fmaxf(m, v3.z); m = fmaxf(m, v3.w);
#pragma unroll
    for (int o = 16; o; o >>= 1) m = fmaxf(m, __shfl_xor_sync(0xffffffffu, m, o));

    float s = 0.f;
    s += __expf(v0.x - m) + __expf(v0.y - m) + __expf(v0.z - m) + __expf(v0.w - m);
    s += __expf(v1.x - m) + __expf(v1.y - m) + __expf(v1.z - m) + __expf(v1.w - m);
    s += __expf(v2.x - m) + __expf(v2.y - m) + __expf(v2.z - m) + __expf(v2.w - m);
    s += __expf(v3.x - m) + __expf(v3.y - m) + __expf(v3.z - m) + __expf(v3.w - m);
#pragma unroll
    for (int o = 16; o; o >>= 1) s += __shfl_xor_sync(0xffffffffu, s, o);

    const float lse = m + __logf(s);
    const float blankLogit = __shfl_sync(0xffffffffu, v3.w, 31);  // element 511

    if (lane == 0) {
        const int b = gw / (T_ * U_);
        const int rem = gw % (T_ * U_);
        const int t = rem / U_;
        const int u = rem % U_;
        const int lbl = (u < U_ - 1) ? targets[b * (U_ - 1) + u] : 0;  // padded -> 0
        const float labelLogit = __ldg(logits + (size_t)gw * D_ + lbl);
        const int gi = (b * T_ + t) * SROW + u;
        g_blank[gi] = (blankLogit - lse) * INV_LN2;   // log2 domain
        g_label[gi] = (labelLogit - lse) * INV_LN2;
    }
}

// ---------------------------------------------------------------------------
// Kernel 2: alpha DP, one CTA per batch. 128 threads stage tiles into SMEM,
// then a SINGLE warp runs the anti-diagonal wavefront fully in registers:
// lane l owns u in {2l, 2l+1}; lane 31 also owns u=64. No __syncthreads in
// the DP loop — the only cross-lane dependency is one shfl_up per diagonal.
// ---------------------------------------------------------------------------
extern __shared__ float s_dyn[];

__global__ void __launch_bounds__(128) dp_kernel(const int* __restrict__ srcLen,
                                                 const int* __restrict__ tgtLen,
                                                 float* __restrict__ out) {
    const int b = blockIdx.x;
    const int tid = threadIdx.x;

    float* sB = s_dyn;                 // [T_ * SROW] blank log2-probs
    float* sL = s_dyn + T_ * SROW;     // [T_ * SROW] label log2-probs

    // Stage (contiguous float4 copy; padding columns carry garbage, never read).
    {
        const float4* gb = reinterpret_cast<const float4*>(g_blank + (size_t)b * T_ * SROW);
        const float4* gl = reinterpret_cast<const float4*>(g_label + (size_t)b * T_ * SROW);
        float4* sb4 = reinterpret_cast<float4*>(sB);
        float4* sl4 = reinterpret_cast<float4*>(sL);
#pragma unroll 4
        for (int i = tid; i < (T_ * SROW) / 4; i += 128) {
            sb4[i] = gb[i];
            sl4[i] = gl[i];
        }
    }
    __syncthreads();
    if (tid >= 32) return;   // only warp 0 runs the DP

    const int lane = tid;
    const int tE = srcLen[b] - 1;
    const int uE = tgtLen[b];
    const int dE = tE + uE;

    if (dE == 0) {   // alpha[0][0] = 0
        if (lane == 0) out[b] = -LN2 * sB[tE * SROW + uE];
        return;
    }

    const int u0 = 2 * lane;
    const int u1 = u0 + 1;

    // Diagonal state (diagonal d-1 at loop top): value of cell (t=d-1-u, u).
    float aE = (lane == 0) ? 0.0f : NEG;   // u = u0
    float aO = NEG;                        // u = u1
    float aX = NEG;                        // u = 64 (lane 31 only)

#pragma unroll 2
    for (int d = 1; d <= dE; ++d) {
        const float nbr = __shfl_up_sync(0xffffffffu, aO, 1);  // prev diag at u0-1

        // even cell: (t0, u0)
        const int t0 = d - u0;
        float newE = aE;
        if (0 <= t0 && t0 < T_) {
            const float ft = (t0 >= 1) ? aE + sB[(t0 - 1) * SROW + u0] : NEG;
            const float fl = (u0 >= 1) ? nbr + sL[t0 * SROW + (u0 - 1)] : NEG;
            newE = lae2(ft, fl);
        }

        // odd cell: (t1, u1) — uses OLD aE as left neighbor
        const int t1 = t0 - 1;
        float newO = aO;
        if (0 <= t1 && t1 < T_) {
            const float ft = (t1 >= 1) ? aO + sB[(t1 - 1) * SROW + u1] : NEG;
            const float fl = aE + sL[t1 * SROW + (u1 - 1)];
            newO = lae2(ft, fl);
        }

        // extra cell u=64 on lane 31 — uses OLD aO as left neighbor
        float newX = aX;
        if (lane == 31) {
            const int tx = d - 64;
            if (0 <= tx && tx < T_) {
                const float ft = (tx >= 1) ? aX + sB[(tx - 1) * SROW + 64] : NEG;
                const float fl = aO + sL[tx * SROW + 63];
                newX = lae2(ft, fl);
            }
        }

        aE = newE; aO = newO; aX = newX;

        if (d == dE) {
            float v = 0.f; bool own = false;
            if (uE == u0)                 { v = aE; own = true; }
            else if (uE == u1)            { v = aO; own = true; }
            else if (uE == 64 && lane == 31) { v = aX; own = true; }
            if (own) out[b] = -LN2 * (v + sB[tE * SROW + uE]);
        }
    }
}

// ---------------------------------------------------------------------------
extern "C" void kernel_launch(void* const* d_in, const int* in_sizes, int n_in,
                              void* d_out, int out_size) {
    const float* logits = (const float*)d_in[0];
    const int* targets = (const int*)d_in[1];
    const int* srcLen = (const int*)d_in[2];
    const int* tgtLen = (const int*)d_in[3];
    float* out = (float*)d_out;

    lse_kernel<<<BTU_ / 8, 256>>>(logits, targets);

    const int smemBytes = 2 * T_ * SROW * (int)sizeof(float);  // 135168 B
    cudaFuncSetAttribute(dp_kernel, cudaFuncAttributeMaxDynamicSharedMemorySize, smemBytes);
    dp_kernel<<<B_, 128, smemBytes>>>(srcLen, tgtLen, out);
}

// round 3
// speedup vs baseline: 1.8895x; 1.6602x over previous
#include <cuda_runtime.h>
#include <cuda_bf16.h>

#define B_ 8
#define T_ 256
#define U_ 65
#define D_ 512
#define BTU_ (B_ * T_ * U_)
#define SROW 66                  // padded row stride (floats)
#define PAD 64                   // NEG-filled pad rows front and back
#define RTOT (T_ + 2 * PAD)      // 384 rows per tile in smem

#define NEG (-1.0e30f)
#define INV_LN2 1.4426950408889634f
#define LN2 0.6931471805599453f

// Scratch: per-(b,t,u) blank/label log2-probs, padded stride 66.
__device__ float g_blank[B_ * T_ * SROW];
__device__ float g_label[B_ * T_ * SROW];

__device__ __forceinline__ float ex2f(float x) {
    float y; asm("ex2.approx.ftz.f32 %0, %1;" : "=f"(y) : "f"(x)); return y;
}
__device__ __forceinline__ float lg2f(float x) {
    float y; asm("lg2.approx.ftz.f32 %0, %1;" : "=f"(y) : "f"(x)); return y;
}
// logaddexp in log2 domain
__device__ __forceinline__ float lae2(float a, float b) {
    float mx = fmaxf(a, b);
    float mn = fminf(a, b);
    return mx + lg2f(1.0f + ex2f(mn - mx));
}

// ---------------------------------------------------------------------------
// Kernel 1: per-row logsumexp over D=512 -> blank/label log2-probs.
// One warp per row; HBM-bound (272MB read once). Also NEG-fills pad column 65.
// ---------------------------------------------------------------------------
__global__ void __launch_bounds__(256) lse_kernel(const float* __restrict__ logits,
                                                  const int* __restrict__ targets) {
    const int gw = (blockIdx.x * 256 + threadIdx.x) >> 5;
    const int lane = threadIdx.x & 31;
    if (gw >= BTU_) return;

    const float4* row4 = reinterpret_cast<const float4*>(logits + (size_t)gw * D_);
    const float4 v0 = row4[lane];
    const float4 v1 = row4[lane + 32];
    const float4 v2 = row4[lane + 64];
    const float4 v3 = row4[lane + 96];

    float m = v0.x;
    m = fmaxf(m, v0.y); m = fmaxf(m, v0.z); m = fmaxf(m, v0.w);
    m = fmaxf(m, v1.x); m = fmaxf(m, v1.y); m = fmaxf(m, v1.z); m = fmaxf(m, v1.w);
    m = fmaxf(m, v2.x); m = fmaxf(m, v2.y); m = fmaxf(m, v2.z); m = fmaxf(m, v2.w);
    m = fmaxf(m, v3.x); m = fmaxf(m, v3.y); m = fmaxf(m, v3.z); m = fmaxf(m, v3.w);
#pragma unroll
    for (int o = 16; o; o >>= 1) m = fmaxf(m, __shfl_xor_sync(0xffffffffu, m, o));

    float s = 0.f;
    s += __expf(v0.x - m) + __expf(v0.y - m) + __expf(v0.z - m) + __expf(v0.w - m);
    s += __expf(v1.x - m) + __expf(v1.y - m) + __expf(v1.z - m) + __expf(v1.w - m);
    s += __expf(v2.x - m) + __expf(v2.y - m) + __expf(v2.z - m) + __expf(v2.w - m);
    s += __expf(v3.x - m) + __expf(v3.y - m) + __expf(v3.z - m) + __expf(v3.w - m);
#pragma unroll
    for (int o = 16; o; o >>= 1) s += __shfl_xor_sync(0xffffffffu, s, o);

    const float lse = m + __logf(s);
    const float blankLogit = __shfl_sync(0xffffffffu, v3.w, 31);

    if (lane == 0) {
        const int b = gw / (T_ * U_);
        const int rem = gw % (T_ * U_);
        const int t = rem / U_;
        const int u = rem % U_;
        const int lbl = (u < U_ - 1) ? targets[b * (U_ - 1) + u] : 0;
        const float labelLogit = __ldg(logits + (size_t)gw * D_ + lbl);
        const int gi = (b * T_ + t) * SROW + u;
        g_blank[gi] = (blankLogit - lse) * INV_LN2;
        g_label[gi] = (labelLogit - lse) * INV_LN2;
        if (u == U_ - 1) {            // NEG-fill padding column 65
            g_blank[gi + 1] = NEG;
            g_label[gi + 1] = NEG;
        }
    }
}

// ---------------------------------------------------------------------------
// Kernel 2: alpha DP, one CTA/batch. NEG-padded tiles in SMEM, single warp,
// fully branchless wavefront: lane l owns u={2l,2l+1}, lane 31 also u=64.
// Loads are unconditional with d-affine addresses (pointer += SROW).
// ---------------------------------------------------------------------------
extern __shared__ float s_dyn[];

__global__ void __launch_bounds__(128) dp_kernel(const int* __restrict__ srcLen,
                                                 const int* __restrict__ tgtLen,
                                                 float* __restrict__ out) {
    const int b = blockIdx.x;
    const int tid = threadIdx.x;

    float* sB = s_dyn;                    // [RTOT * SROW]
    float* sL = s_dyn + RTOT * SROW;      // [RTOT * SROW]

    {   // NEG-fill pad rows (front + back), then copy valid rows. Disjoint regions.
        const float4 ng = make_float4(NEG, NEG, NEG, NEG);
        float4* sb4 = reinterpret_cast<float4*>(sB);
        float4* sl4 = reinterpret_cast<float4*>(sL);
        const int padQ = (PAD * SROW) / 4;           // 1056
        const int backQ = ((PAD + T_) * SROW) / 4;   // 5280
        for (int i = tid; i < padQ; i += 128) {
            sb4[i] = ng;          sl4[i] = ng;
            sb4[backQ + i] = ng;  sl4[backQ + i] = ng;
        }
        const float4* gb = reinterpret_cast<const float4*>(g_blank + (size_t)b * T_ * SROW);
        const float4* gl = reinterpret_cast<const float4*>(g_label + (size_t)b * T_ * SROW);
#pragma unroll 4
        for (int i = tid; i < (T_ * SROW) / 4; i += 128) {
            sb4[padQ + i] = gb[i];
            sl4[padQ + i] = gl[i];
        }
    }
    __syncthreads();
    if (tid >= 32) return;

    const int lane = tid;
    const int tE = srcLen[b] - 1;
    const int uE = tgtLen[b];
    const int dE = tE + uE;

    const int u0 = 2 * lane;
    const int u1 = u0 + 1;

    float aE = (lane == 0) ? 0.0f : NEG;   // u = u0 on current diagonal
    float aO = NEG;                        // u = u1
    float aX = NEG;                        // u = 64 (lane 31)

    // d-affine load pointers at d = 1 (t0 = 1 - u0):
    // even blank  : row (t0-1),  col u0
    // even label  : row  t0,     col u0-1  (lane0 hits NEG pad col of prev row)
    // odd  blank  : row (t0-2),  col u1
    // odd  label  : row (t0-1),  col u0
    // x    blank  : row (d-65),  col 64
    // x    label  : row (d-64),  col 63
    const float* pB0 = sB + (PAD + (1 - u0) - 1) * SROW + u0;
    const float* pL0 = sL + (PAD + (1 - u0)) * SROW + (u0 - 1);
    const float* pB1 = sB + (PAD + (1 - u0) - 2) * SROW + u1;
    const float* pL1 = sL + (PAD + (1 - u0) - 1) * SROW + u0;
    const float* pBx = sB + (PAD + 1 - 65) * SROW + 64;
    const float* pLx = sL + (PAD + 1 - 64) * SROW + 63;

    int t0 = 1 - u0;

#pragma unroll 4
    for (int d = 1; d <= dE; ++d) {
        const float xB0 = *pB0;
        const float xL0 = *pL0;
        const float xB1 = *pB1;
        const float xL1 = *pL1;
        const float xBx = *pBx;
        const float xLx = *pLx;

        const float nbr = __shfl_up_sync(0xffffffffu, aO, 1);

        const float rE = lae2(aE + xB0, nbr + xL0);
        const float rO = lae2(aO + xB1, aE + xL1);
        const float rX = lae2(aX + xBx, aO + xLx);

        const bool actE = (unsigned)t0 < (unsigned)T_;
        const bool actO = (unsigned)(t0 - 1) < (unsigned)T_;
        const bool actX = ((unsigned)(d - 64) < (unsigned)T_) && (lane == 31);

        aE = actE ? rE : aE;
        aO = actO ? rO : aO;
        aX = actX ? rX : aX;

        pB0 += SROW; pL0 += SROW; pB1 += SROW; pL1 += SROW; pBx += SROW; pLx += SROW;
        ++t0;
    }

    const bool ownE = (uE == u0);
    const bool ownO = (uE == u1);
    const bool ownX = (uE == 64) && (lane == 31);
    if (ownE || ownO || ownX) {
        const float alphaF = ownE ? aE : (ownO ? aO : aX);
        out[b] = -LN2 * (alphaF + sB[(PAD + tE) * SROW + uE]);
    }
}

// ---------------------------------------------------------------------------
extern "C" void kernel_launch(void* const* d_in, const int* in_sizes, int n_in,
                              void* d_out, int out_size) {
    const float* logits = (const float*)d_in[0];
    const int* targets = (const int*)d_in[1];
    const int* srcLen = (const int*)d_in[2];
    const int* tgtLen = (const int*)d_in[3];
    float* out = (float*)d_out;

    lse_kernel<<<BTU_ / 8, 256>>>(logits, targets);

    const int smemBytes = 2 * RTOT * SROW * (int)sizeof(float);  // 202752 B
    cudaFuncSetAttribute(dp_kernel, cudaFuncAttributeMaxDynamicSharedMemorySize, smemBytes);
    dp_kernel<<<B_, 128, smemBytes>>>(srcLen, tgtLen, out);
}